// round 9
// baseline (speedup 1.0000x reference)
#include <cuda_runtime.h>
#include <cuda_bf16.h>
#include <math.h>

#define BB 32
#define TT 24
#define NN 1024
#define NCTA 128
#define NTHR 512
#define GRP 4                  // CTAs per batch

// ---------------- fp32 scratch ----------------
#define OFF_AX   0                          // 3 groups x (B,N,16) = A@x_t
#define OFF_RS   (3 * BB * NN * 16)         // (B,N) rowsum(A)
#define OFF_TVF  (OFF_RS + BB * NN)         // (B,2)
#define SCRATCH_FLOATS (OFF_TVF + BB * 2)

__device__ float d_scratch[SCRATCH_FLOATS];
// A bf16 packed in mma-fragment order: per CTA 32768 uint4
// index: ((blk*64 + ks)*32 + lane), blk = 16-row block id (rowbase = blk*16)
__device__ uint4 d_Apk[(size_t)BB * NN * NN / 8];
__device__ __nv_bfloat16 d_xbf[(size_t)BB * 48 * NN];     // X^T: 0-15 h1, 16-31 h2, 32-47 r*h
__device__ __nv_bfloat16 d_xt [(size_t)BB * 48 * NN];     // gathered x_t, transposed
// per-batch barrier state, one padded line per batch
__device__ unsigned g_bcnt[BB * 32];
__device__ volatile unsigned g_bgen[BB * 32];

// smem word-offsets (dynamic)
#define XPW 516          // X smem pitch in words (2048B data + 16B pad)
#define SPW 49           // stage pitch in floats
#define SW_X    0        // X: 32 rows x 516 words
#define SW_STG  16512    // stage: 256 x 49 floats
#define SW_W1RU 29056
#define SW_W2RU 29632
#define SW_W1CP 30656
#define SW_W2CP 30944
#define SW_B1RU 31456
#define SW_B2RU 31488
#define SW_B1CP 31520
#define SW_B2CP 31536
#define SW_GCNW 31552
#define SW_GCNB 31584
#define SMEM_WORDS 31586
#define SMEM_BYTES (SMEM_WORDS * 4 + 8)

__device__ __forceinline__ float sigf(float x) { return 1.0f / (1.0f + expf(-x)); }

__device__ __forceinline__ void cpa16s(unsigned* sm, const void* gm) {
    unsigned sa = (unsigned)__cvta_generic_to_shared(sm);
    asm volatile("cp.async.cg.shared.global [%0], [%1], 16;" :: "r"(sa), "l"(gm) : "memory");
}
#define CP_COMMIT() asm volatile("cp.async.commit_group;" ::: "memory")
#define CP_WAIT(n)  asm volatile("cp.async.wait_group %0;" :: "n"(n) : "memory")

__device__ __forceinline__ unsigned long long dup2(float x) {
    unsigned long long r; unsigned u = __float_as_uint(x);
    asm("mov.b64 %0, {%1, %1};" : "=l"(r) : "r"(u));
    return r;
}
__device__ __forceinline__ void fma2(unsigned long long& s, unsigned long long a, unsigned long long w) {
    asm("fma.rn.f32x2 %0, %1, %2, %0;" : "+l"(s) : "l"(a), "l"(w));
}
__device__ __forceinline__ void unpack2(unsigned long long s, float& x, float& y) {
    unsigned lo, hi; asm("mov.b64 {%0, %1}, %2;" : "=r"(lo), "=r"(hi) : "l"(s));
    x = __uint_as_float(lo); y = __uint_as_float(hi);
}
__device__ __forceinline__ unsigned packbf2(float2 v) {
    __nv_bfloat162 b = __float22bfloat162_rn(v);
    return *(unsigned*)&b;
}

// per-batch barrier (R7/R8-proven: all-thread gpu fence before the quorum)
__device__ __forceinline__ void batchbar(int b) {
    __threadfence();
    __syncthreads();
    if (threadIdx.x == 0) {
        unsigned gen = g_bgen[b * 32];
        if (atomicAdd(&g_bcnt[b * 32], 1) == GRP - 1) {
            g_bcnt[b * 32] = 0;
            __threadfence();
            g_bgen[b * 32] = gen + 1;
        } else {
            while (g_bgen[b * 32] == gen) __nanosleep(32);
        }
        __threadfence();
    }
    __syncthreads();
}

// ---------- GEMM phase: acc[256 own rows x C]; warp w owns rows w*16..w*16+15 ----------
// X^T loaded whole into smem once; A streamed via LDG.128 from the fragment-
// ordered pack with a depth-8 register ring (8 outstanding loads/warp).
template <int C>
__device__ __forceinline__ void gemmL(const uint4* __restrict__ Apk,
                                      const __nv_bfloat16* __restrict__ Xb,
                                      unsigned* smem_u, float acc[C / 8][4]) {
    const int tid = threadIdx.x, w = tid >> 5, lane = tid & 31;
    unsigned* Xs = smem_u + SW_X;

    // load full X^T (C rows x 2KB) into smem
#pragma unroll
    for (int q = 0; q < C / 4; q++) {
        int i = tid + q * NTHR;
        int c = i >> 7, ch = i & 127;
        cpa16s(Xs + c * XPW + ch * 4, Xb + (size_t)c * NN + ch * 8);
    }
    CP_COMMIT();
    CP_WAIT(0);
    __syncthreads();

#pragma unroll
    for (int nt = 0; nt < C / 8; nt++)
#pragma unroll
        for (int q = 0; q < 4; q++) acc[nt][q] = 0.f;

    const unsigned xB = (unsigned)__cvta_generic_to_shared(Xs);
    const unsigned boff = ((unsigned)(lane & 7) * XPW + ((lane >> 3) & 1) * 4) * 4;
    const uint4* Aw = Apk + ((size_t)w * 64) * 32 + lane;

    uint4 r0[8];
#pragma unroll
    for (int p = 0; p < 8; p++) r0[p] = Aw[p * 32];

    for (int kb = 0; kb < 8; kb++) {
#pragma unroll
        for (int q = 0; q < 8; q++) {
            const int ks = kb * 8 + q;
            unsigned bf[C / 8][2];
#pragma unroll
            for (int nt = 0; nt < C / 8; nt++) {
                unsigned ad = xB + boff + (unsigned)nt * 8 * XPW * 4 + (unsigned)ks * 32;
                asm volatile("ldmatrix.sync.aligned.m8n8.x2.shared.b16 {%0,%1}, [%2];"
                             : "=r"(bf[nt][0]), "=r"(bf[nt][1]) : "r"(ad));
            }
            uint4 fa = r0[q];
            if (kb < 7) r0[q] = Aw[(ks + 8) * 32];
#pragma unroll
            for (int nt = 0; nt < C / 8; nt++) {
                asm volatile(
                    "mma.sync.aligned.m16n8k16.row.col.f32.bf16.bf16.f32 "
                    "{%0,%1,%2,%3},{%4,%5,%6,%7},{%8,%9},{%0,%1,%2,%3};"
                    : "+f"(acc[nt][0]), "+f"(acc[nt][1]), "+f"(acc[nt][2]), "+f"(acc[nt][3])
                    : "r"(fa.x), "r"(fa.y), "r"(fa.z), "r"(fa.w),
                      "r"(bf[nt][0]), "r"(bf[nt][1]));
            }
        }
    }
}

// write acc fragments to smem stage (256 rows, pitch SPW) at column offset
template <int C>
__device__ __forceinline__ void stageStore(float* stage, const float acc[C / 8][4], int colOff) {
    const int lane = threadIdx.x & 31, w = threadIdx.x >> 5;
    const int g = lane >> 2, c2 = (lane & 3) * 2;
    const int rr = w * 16 + g;
#pragma unroll
    for (int nt = 0; nt < C / 8; nt++) {
        int col = colOff + nt * 8 + c2;
        stage[rr * SPW + col]           = acc[nt][0];
        stage[rr * SPW + col + 1]       = acc[nt][1];
        stage[(rr + 8) * SPW + col]     = acc[nt][2];
        stage[(rr + 8) * SPW + col + 1] = acc[nt][3];
    }
}

// ================= persistent kernel =================
__global__ void __launch_bounds__(NTHR, 1) persistK(
    const float* __restrict__ A, const float* __restrict__ recent,
    const float* __restrict__ g1rW, const float* __restrict__ g1rb,
    const float* __restrict__ g1uW, const float* __restrict__ g1ub,
    const float* __restrict__ g1cW, const float* __restrict__ g1cb,
    const float* __restrict__ g2rW, const float* __restrict__ g2rb,
    const float* __restrict__ g2uW, const float* __restrict__ g2ub,
    const float* __restrict__ g2cW, const float* __restrict__ g2cb,
    const float* __restrict__ gcnW, const float* __restrict__ gcnb,
    float* __restrict__ out) {
    extern __shared__ unsigned smem_u[];
    float* stage = (float*)(smem_u + SW_STG);

    const int tid = threadIdx.x, w = tid >> 5, lane = tid & 31;
    const int b = blockIdx.x >> 2, rb = blockIdx.x & 3;
    const int row0 = rb * 256;
    const int row = tid & 255, jh = tid >> 8, j0 = jh * 8;
    const int n0 = row0 + row;
    const size_t r0 = (size_t)b * NN + n0;

    // ---- weight tables into smem ----
    {
        float2* W1 = (float2*)(smem_u + SW_W1RU);
        for (int i = tid; i < 288; i += NTHR) W1[i] = make_float2(g1rW[i], g1uW[i]);
        float2* W2 = (float2*)(smem_u + SW_W2RU);
        for (int i = tid; i < 512; i += NTHR) W2[i] = make_float2(g2rW[i], g2uW[i]);
        float2* C1 = (float2*)(smem_u + SW_W1CP);
        for (int i = tid; i < 144; i += NTHR) {
            int k = i >> 3, m = i & 7;
            C1[i] = make_float2(g1cW[(2 * m) * 18 + k], g1cW[(2 * m + 1) * 18 + k]);
        }
        float2* C2 = (float2*)(smem_u + SW_W2CP);
        for (int i = tid; i < 256; i += NTHR) {
            int k = i >> 3, m = i & 7;
            C2[i] = make_float2(g2cW[(2 * m) * 32 + k], g2cW[(2 * m + 1) * 32 + k]);
        }
        if (tid < 16) ((float2*)(smem_u + SW_B1RU))[tid] = make_float2(g1rb[tid], g1ub[tid]);
        else if (tid < 32) ((float2*)(smem_u + SW_B2RU))[tid - 16] = make_float2(g2rb[tid - 16], g2ub[tid - 16]);
        else if (tid < 40) ((float2*)(smem_u + SW_B1CP))[tid - 32] = make_float2(g1cb[2 * (tid - 32)], g1cb[2 * (tid - 32) + 1]);
        else if (tid < 48) ((float2*)(smem_u + SW_B2CP))[tid - 40] = make_float2(g2cb[2 * (tid - 40)], g2cb[2 * (tid - 40) + 1]);
        else if (tid < 80) { int i = tid - 48; ((float*)(smem_u + SW_GCNW))[i] = gcnW[(i >> 4) * 80 + (i & 15)]; }
        else if (tid < 82) ((float*)(smem_u + SW_GCNB))[tid - 80] = gcnb[tid - 80];
    }

    // ---- pack own A slice into mma-fragment order (bf16); warp w does block w ----
    const float* Arow = A + ((size_t)b * NN + row0) * NN;
    uint4* pk = d_Apk + (size_t)blockIdx.x * 32768;
    {
        const int gr = lane >> 2, k0b = (lane & 3) * 2;
        const int blk = w;                                   // 16 warps, 16 blocks
        int rowbase = blk * 16;
        const float* rp0 = Arow + (size_t)(rowbase + gr) * NN;
        const float* rp8 = Arow + (size_t)(rowbase + gr + 8) * NN;
        for (int ks = 0; ks < 64; ks++) {
            int k0 = ks * 16 + k0b;
            uint4 u;
            u.x = packbf2(*(const float2*)(rp0 + k0));
            u.y = packbf2(*(const float2*)(rp8 + k0));
            u.z = packbf2(*(const float2*)(rp0 + k0 + 8));
            u.w = packbf2(*(const float2*)(rp8 + k0 + 8));
            pk[((size_t)blk * 64 + ks) * 32 + lane] = u;
        }
    }

    // ---- exact fp32 rowsum (warp per 16 rows) ----
    for (int j = 0; j < 16; j++) {
        const int r = w * 16 + j;
        const float4* ap = (const float4*)(Arow + (size_t)r * NN);
        float s = 0.f;
#pragma unroll 4
        for (int q = lane; q < 256; q += 32) {
            float4 v = ap[q];
            s += (v.x + v.y) + (v.z + v.w);
        }
#pragma unroll
        for (int o = 16; o; o >>= 1) s += __shfl_xor_sync(~0u, s, o);
        if (!lane) d_scratch[OFF_RS + (size_t)b * NN + row0 + r] = s;
    }

    // ---- gather x_t (transposed bf16, split by jh) + zero h columns ----
    {
        const float2* rp = (const float2*)recent;
        for (int t = jh * 12; t < jh * 12 + 12; t++) {
            float2 v = rp[(size_t)(b * TT + t) * NN + n0];
            d_xt[((size_t)b * 48 + 2 * t) * NN + n0]     = __float2bfloat16_rn(v.x);
            d_xt[((size_t)b * 48 + 2 * t + 1) * NN + n0] = __float2bfloat16_rn(v.y);
        }
        __nv_bfloat16 z = __float2bfloat16_rn(0.f);
        for (int c = jh * 16; c < jh * 16 + 16; c++) d_xbf[((size_t)b * 48 + c) * NN + n0] = z;
    }

    float h1[8], h2[8], uu[8];
#pragma unroll
    for (int k = 0; k < 8; k++) { h1[k] = 0.f; h2[k] = 0.f; }

    batchbar(b);

    // ---- A @ x_t for all 24 timesteps (CTA-local outputs) ----
    for (int g = 0; g < 3; g++) {
        float a16[2][4];
        gemmL<16>(pk, d_xt + ((size_t)b * 48 + g * 16) * NN, smem_u, a16);
        stageStore<16>(stage, a16, 0);
        __syncthreads();
        float* axp = d_scratch + OFF_AX + (size_t)g * (BB * NN * 16) + r0 * 16 + jh * 8;
        const float* srow = stage + row * SPW + jh * 8;
        ((float4*)axp)[0] = make_float4(srow[0], srow[1], srow[2], srow[3]);
        ((float4*)axp)[1] = make_float4(srow[4], srow[5], srow[6], srow[7]);
        __syncthreads();
    }

    const __nv_bfloat16* xbB = d_xbf + (size_t)b * 48 * NN;
    __nv_bfloat16* xo_h1 = d_xbf + ((size_t)b * 48 + 0) * NN + n0;
    __nv_bfloat16* xo_h2 = d_xbf + ((size_t)b * 48 + 16) * NN + n0;
    __nv_bfloat16* xo_rh = d_xbf + ((size_t)b * 48 + 32) * NN + n0;

    const unsigned long long* W1ru = (const unsigned long long*)(smem_u + SW_W1RU);
    const unsigned long long* W2ru = (const unsigned long long*)(smem_u + SW_W2RU);
    const unsigned long long* W1cp = (const unsigned long long*)(smem_u + SW_W1CP);
    const unsigned long long* W2cp = (const unsigned long long*)(smem_u + SW_W2CP);
    const unsigned long long* B1ru = (const unsigned long long*)(smem_u + SW_B1RU);
    const unsigned long long* B2ru = (const unsigned long long*)(smem_u + SW_B2RU);
    const unsigned long long* B1cp = (const unsigned long long*)(smem_u + SW_B1CP);
    const unsigned long long* B2cp = (const unsigned long long*)(smem_u + SW_B2CP);

    for (int t = 0; t < TT; t++) {
        const int g = t >> 3, p = t & 7;
        const float* axp = d_scratch + OFF_AX + (size_t)g * (BB * NN * 16) + r0 * 16 + p * 2;

        // ---- phase 1: [A@h1 | A@h2] -> stage cols 0-31; gates1 ----
        {
            float a32[4][4];
            gemmL<32>(pk, xbB, smem_u, a32);
            stageStore<32>(stage, a32, 0);
            __syncthreads();
            const float* srow = stage + row * SPW;
            float2 axv = *(const float2*)axp;
            float xh[18];
            xh[0] = axv.x; xh[1] = axv.y;
#pragma unroll
            for (int k = 0; k < 16; k++) xh[2 + k] = srow[k];
#pragma unroll
            for (int jj = 0; jj < 8; jj++) {
                const int j = j0 + jj;
                unsigned long long s = B1ru[j];
#pragma unroll
                for (int k = 0; k < 18; k++) fma2(s, dup2(xh[k]), W1ru[j * 18 + k]);
                float sr, su; unpack2(s, sr, su);
                uu[jj] = sigf(su);
                xo_rh[(size_t)j * NN] = __float2bfloat16_rn(sigf(sr) * h1[jj]);
            }
            __syncthreads();
        }
        batchbar(b);

        // ---- phase 2: A@(r1*h1) -> stage cols 0-15; gates2 -> h1' ----
        {
            float a16[2][4];
            gemmL<16>(pk, xbB + (size_t)32 * NN, smem_u, a16);
            stageStore<16>(stage, a16, 0);
            __syncthreads();
            const float* srow = stage + row * SPW;
            float2 axv = *(const float2*)axp;
            float xh[18];
            xh[0] = axv.x; xh[1] = axv.y;
#pragma unroll
            for (int k = 0; k < 16; k++) xh[2 + k] = srow[k];
            unsigned long long sm[4];
#pragma unroll
            for (int m = 0; m < 4; m++) sm[m] = B1cp[jh * 4 + m];
#pragma unroll
            for (int k = 0; k < 18; k++) {
                unsigned long long a = dup2(xh[k]);
#pragma unroll
                for (int m = 0; m < 4; m++) fma2(sm[m], a, W1cp[k * 8 + jh * 4 + m]);
            }
#pragma unroll
            for (int m = 0; m < 4; m++) {
                float c0, c1; unpack2(sm[m], c0, c1);
                int jj = 2 * m;
                h1[jj]     = uu[jj]     * h1[jj]     + (1.f - uu[jj])     * tanhf(c0);
                h1[jj + 1] = uu[jj + 1] * h1[jj + 1] + (1.f - uu[jj + 1]) * tanhf(c1);
                xo_h1[(size_t)(j0 + jj) * NN]     = __float2bfloat16_rn(h1[jj]);
                xo_h1[(size_t)(j0 + jj + 1) * NN] = __float2bfloat16_rn(h1[jj + 1]);
            }
            __syncthreads();
        }
        batchbar(b);

        // ---- phase 3: A@h1' -> stage cols 32-47; gates3 (ah2 from cols 16-31) ----
        {
            float a16[2][4];
            gemmL<16>(pk, xbB, smem_u, a16);
            stageStore<16>(stage, a16, 32);
            __syncthreads();
            const float* srow = stage + row * SPW;
#pragma unroll
            for (int jj = 0; jj < 8; jj++) {
                const int j = j0 + jj;
                unsigned long long s = B2ru[j];
#pragma unroll
                for (int k = 0; k < 16; k++) fma2(s, dup2(srow[32 + k]), W2ru[j * 32 + k]);
#pragma unroll
                for (int k = 0; k < 16; k++) fma2(s, dup2(srow[16 + k]), W2ru[j * 32 + 16 + k]);
                float sr, su; unpack2(s, sr, su);
                uu[jj] = sigf(su);
                xo_rh[(size_t)j * NN] = __float2bfloat16_rn(sigf(sr) * h2[jj]);
            }
            __syncthreads();
        }
        batchbar(b);

        // ---- phase 4: A@(r2*h2) -> stage cols 0-15; gates4 (ah1p from cols 32-47) ----
        {
            float a16[2][4];
            gemmL<16>(pk, xbB + (size_t)32 * NN, smem_u, a16);
            stageStore<16>(stage, a16, 0);
            __syncthreads();
            const float* srow = stage + row * SPW;
            unsigned long long sm[4];
#pragma unroll
            for (int m = 0; m < 4; m++) sm[m] = B2cp[jh * 4 + m];
#pragma unroll
            for (int k = 0; k < 16; k++) {
                unsigned long long a = dup2(srow[32 + k]);
#pragma unroll
                for (int m = 0; m < 4; m++) fma2(sm[m], a, W2cp[k * 8 + jh * 4 + m]);
            }
#pragma unroll
            for (int k = 0; k < 16; k++) {
                unsigned long long a = dup2(srow[k]);
#pragma unroll
                for (int m = 0; m < 4; m++) fma2(sm[m], a, W2cp[(16 + k) * 8 + jh * 4 + m]);
            }
#pragma unroll
            for (int m = 0; m < 4; m++) {
                float c0, c1; unpack2(sm[m], c0, c1);
                int jj = 2 * m;
                h2[jj]     = uu[jj]     * h2[jj]     + (1.f - uu[jj])     * tanhf(c0);
                h2[jj + 1] = uu[jj + 1] * h2[jj + 1] + (1.f - uu[jj + 1]) * tanhf(c1);
                xo_h2[(size_t)(j0 + jj) * NN]     = __float2bfloat16_rn(h2[jj]);
                xo_h2[(size_t)(j0 + jj + 1) * NN] = __float2bfloat16_rn(h2[jj + 1]);
            }
            __syncthreads();
        }
        batchbar(b);
    }

    // ---- final: A@h2 + folded trend/feat, tanh, write output ----
    {
        float a16[2][4];
        gemmL<16>(pk, xbB + (size_t)16 * NN, smem_u, a16);
        stageStore<16>(stage, a16, 0);
        __syncthreads();
        if (jh == 0) {
            const float* srow = stage + row * SPW;
            const float* gw = (const float*)(smem_u + SW_GCNW);
            const float* gb = (const float*)(smem_u + SW_GCNB);
            float rs = d_scratch[OFF_RS + r0];
            float o0 = gb[0] + rs * d_scratch[OFF_TVF + b * 2];
            float o1 = gb[1] + rs * d_scratch[OFF_TVF + b * 2 + 1];
#pragma unroll
            for (int c = 0; c < 16; c++) {
                o0 += srow[c] * gw[c];
                o1 += srow[c] * gw[16 + c];
            }
            *(float2*)(out + r0 * 2) = make_float2(tanhf(o0), tanhf(o1));
        }
    }
}

// ---- 2-layer LSTM + feat FF folded into tvf (B,2) ----
__global__ __launch_bounds__(1024) void prepK(
    const float* __restrict__ trend, const float* __restrict__ tf,
    const float* __restrict__ Wih0, const float* __restrict__ Whh0,
    const float* __restrict__ bih0, const float* __restrict__ bhh0,
    const float* __restrict__ Wih1, const float* __restrict__ Whh1,
    const float* __restrict__ bih1, const float* __restrict__ bhh1,
    const float* __restrict__ ffW, const float* __restrict__ ffb,
    const float* __restrict__ gcnW) {
    __shared__ float h1s[32][32], c1s[32][32], h2s[32][32], c2s[32][32], feats[32][32];
    int tid = threadIdx.x;
    int b = tid >> 5, j = tid & 31;
    h1s[b][j] = 0.f; c1s[b][j] = 0.f; h2s[b][j] = 0.f; c2s[b][j] = 0.f;
    __syncthreads();

    for (int t = 0; t < TT; t++) {
        float x0 = trend[(b * TT + t) * 2 + 0];
        float x1 = trend[(b * TT + t) * 2 + 1];
        float g0[4];
#pragma unroll
        for (int g = 0; g < 4; g++) {
            int idx = g * 32 + j;
            float s = bih0[idx] + bhh0[idx] + Wih0[idx * 2] * x0 + Wih0[idx * 2 + 1] * x1;
            for (int k = 0; k < 32; k++) s += Whh0[idx * 32 + k] * h1s[b][k];
            g0[g] = s;
        }
        float c1 = sigf(g0[1]) * c1s[b][j] + sigf(g0[0]) * tanhf(g0[2]);
        float h1 = sigf(g0[3]) * tanhf(c1);
        __syncthreads();
        h1s[b][j] = h1; c1s[b][j] = c1;
        __syncthreads();

        float g1[4];
#pragma unroll
        for (int g = 0; g < 4; g++) {
            int idx = g * 32 + j;
            float s = bih1[idx] + bhh1[idx];
            for (int k = 0; k < 32; k++)
                s += Wih1[idx * 32 + k] * h1s[b][k] + Whh1[idx * 32 + k] * h2s[b][k];
            g1[g] = s;
        }
        float c2 = sigf(g1[1]) * c2s[b][j] + sigf(g1[0]) * tanhf(g1[2]);
        float h2 = sigf(g1[3]) * tanhf(c2);
        __syncthreads();
        h2s[b][j] = h2; c2s[b][j] = c2;
        __syncthreads();
    }

    float s = ffb[j];
    for (int k = 0; k < 31; k++) s += tf[b * 31 + k] * ffW[j * 31 + k];
    feats[b][j] = fmaxf(s, 0.f);
    __syncthreads();

    if (tid < 64) {
        int bb = tid >> 1, f = tid & 1;
        float s2 = 0.f;
        for (int c = 0; c < 32; c++)
            s2 += h2s[bb][c] * gcnW[f * 80 + 16 + c] + feats[bb][c] * gcnW[f * 80 + 48 + c];
        d_scratch[OFF_TVF + bb * 2 + f] = s2;
    }
}

// ================================== launcher ===================================
extern "C" void kernel_launch(void* const* d_in, const int* in_sizes, int n_in,
                              void* d_out, int out_size) {
    const float* recent = (const float*)d_in[0];
    const float* trend  = (const float*)d_in[1];
    const float* A      = (const float*)d_in[2];
    const float* tf     = (const float*)d_in[3];
    const float* g1rW = (const float*)d_in[4],  *g1rb = (const float*)d_in[5];
    const float* g1uW = (const float*)d_in[6],  *g1ub = (const float*)d_in[7];
    const float* g1cW = (const float*)d_in[8],  *g1cb = (const float*)d_in[9];
    const float* g2rW = (const float*)d_in[10], *g2rb = (const float*)d_in[11];
    const float* g2uW = (const float*)d_in[12], *g2ub = (const float*)d_in[13];
    const float* g2cW = (const float*)d_in[14], *g2cb = (const float*)d_in[15];
    const float* Wih0 = (const float*)d_in[16], *Whh0 = (const float*)d_in[17];
    const float* bih0 = (const float*)d_in[18], *bhh0 = (const float*)d_in[19];
    const float* Wih1 = (const float*)d_in[20], *Whh1 = (const float*)d_in[21];
    const float* bih1 = (const float*)d_in[22], *bhh1 = (const float*)d_in[23];
    const float* ffW  = (const float*)d_in[24], *ffb  = (const float*)d_in[25];
    const float* gcnW = (const float*)d_in[26], *gcnb = (const float*)d_in[27];
    float* out = (float*)d_out;

    cudaFuncSetAttribute(persistK, cudaFuncAttributeMaxDynamicSharedMemorySize, SMEM_BYTES);

    prepK<<<1, 1024>>>(trend, tf, Wih0, Whh0, bih0, bhh0,
                       Wih1, Whh1, bih1, bhh1, ffW, ffb, gcnW);
    persistK<<<NCTA, NTHR, SMEM_BYTES>>>(A, recent,
                                         g1rW, g1rb, g1uW, g1ub, g1cW, g1cb,
                                         g2rW, g2rb, g2uW, g2ub, g2cW, g2cb,
                                         gcnW, gcnb, out);
}